// round 17
// baseline (speedup 1.0000x reference)
#include <cuda_runtime.h>
#include <math.h>

// Problem constants
#define B_    256
#define I_    1152
#define J_    10
#define DIN   8
#define DOUT  16
#define KDIM  (I_*DIN)        // 9216
#define NDIM  (J_*DOUT)       // 160
#define SPLITK 72
#define KCHUNK (KDIM/SPLITK)  // 128
#define KK    16              // smem k-tile

// ---- scratch (__device__ globals: allocation-free rule) ----
__device__ float g_Wt[KDIM*NDIM];           // Wt[ik][jd] = W[i,j,d,k]
__device__ float g_Wc[KDIM*NDIM];           // coupling-scaled: c[i][j] * Wt[ik][jd]
__device__ float g_P [SPLITK*B_*NDIM];      // split-K partials of s
__device__ float g_G [KDIM*NDIM];           // G[ik][jd] = sum_b x[b,ik]*s[b,jd]
__device__ float g_s [B_*NDIM];             // squashed s (iters 1,2)
__device__ float g_b [I_*J_];               // routing logits

// ---------------------------------------------------------------------------
// init b, rearrange W -> Wt, and write g_Wc = 0.1*Wt (softmax of zero logits)
__global__ void k_wtinit(const float* __restrict__ W) {
    int idx = blockIdx.x*256 + threadIdx.x;
    if (idx < I_*J_) g_b[idx] = 0.0f;
    if (idx >= KDIM*NDIM) return;
    int ik = idx / NDIM, jd = idx - ik*NDIM;
    int i = ik >> 3, k = ik & 7;
    int j = jd >> 4, d = jd & 15;
    float w = W[((i*J_ + j)*DOUT + d)*DIN + k];
    g_Wt[idx] = w;
    g_Wc[idx] = 0.1f * w;
}

// ---------------------------------------------------------------------------
// S-GEMM: P[sp][m][n] = sum_{k in split} x[m][k] * Wc[k][n]
// M=256, N=160, K=9216. grid (4, 72) = 288 blocks, 256 threads (2 CTAs/SM).
// Register-prefetch double-buffered tiles; micro-tile 4(m) x 10(n).
__global__ __launch_bounds__(256) void k_sgemm(const float* __restrict__ x) {
    __shared__ float Xs[2][64*17];     // [m][k] pad 17
    __shared__ float Ws[2][KK*NDIM];   // [k][n]

    const int tid = threadIdx.x;
    const int tx  = tid & 15;          // n-thread / k-load col
    const int ty  = tid >> 4;          // m-thread
    const int m0  = blockIdx.x * 64;
    const int kbase = blockIdx.y * KCHUNK;
    const int T = KCHUNK / KK;         // 8 tiles

    float acc[4][10];
#pragma unroll
    for (int r = 0; r < 4; ++r)
#pragma unroll
        for (int q = 0; q < 10; ++q) acc[r][q] = 0.0f;

    float xr[4], wr[10];
    // prefetch tile 0
    {
        const int k0 = kbase;
#pragma unroll
        for (int p = 0; p < 4; ++p)
            xr[p] = x[(m0 + ty + 16*p)*KDIM + k0 + tx];
#pragma unroll
        for (int p = 0; p < 10; ++p) {
            int idx = tid + 256*p;
            int kk = idx / NDIM, n = idx - kk*NDIM;
            wr[p] = g_Wc[(k0 + kk)*NDIM + n];
        }
    }

    for (int t = 0; t < T; ++t) {
        const int buf = t & 1;
        // deposit prefetched tile
#pragma unroll
        for (int p = 0; p < 4; ++p)
            Xs[buf][(ty + 16*p)*17 + tx] = xr[p];
#pragma unroll
        for (int p = 0; p < 10; ++p) {
            int idx = tid + 256*p;
            int kk = idx / NDIM, n = idx - kk*NDIM;
            Ws[buf][kk*NDIM + n] = wr[p];
        }
        __syncthreads();

        // prefetch next tile (overlaps with compute)
        if (t + 1 < T) {
            const int k0 = kbase + (t+1)*KK;
#pragma unroll
            for (int p = 0; p < 4; ++p)
                xr[p] = x[(m0 + ty + 16*p)*KDIM + k0 + tx];
#pragma unroll
            for (int p = 0; p < 10; ++p) {
                int idx = tid + 256*p;
                int kk = idx / NDIM, n = idx - kk*NDIM;
                wr[p] = g_Wc[(k0 + kk)*NDIM + n];
            }
        }

#pragma unroll
        for (int kk = 0; kk < KK; ++kk) {
            float xv[4], wv[10];
#pragma unroll
            for (int r = 0; r < 4; ++r) xv[r] = Xs[buf][(ty*4 + r)*17 + kk];
#pragma unroll
            for (int q = 0; q < 10; ++q) wv[q] = Ws[buf][kk*NDIM + tx + 16*q];
#pragma unroll
            for (int r = 0; r < 4; ++r)
#pragma unroll
                for (int q = 0; q < 10; ++q) acc[r][q] += xv[r]*wv[q];
        }
        // note: no trailing sync needed — next deposit targets the other buffer,
        // and re-use of this buffer (t+2) is fenced by the sync at t+1.
    }

    float* P = g_P + blockIdx.y*(B_*NDIM);
#pragma unroll
    for (int r = 0; r < 4; ++r) {
        int m = m0 + ty*4 + r;
#pragma unroll
        for (int q = 0; q < 10; ++q)
            P[m*NDIM + tx + 16*q] = acc[r][q];
    }
}

// ---------------------------------------------------------------------------
// reduce 72 split-K partials + squash. block (160,4): 4 y-threads x 18 each.
__global__ void k_redsquash(float* __restrict__ out, int use_out) {
    const int b  = blockIdx.x;
    const int jd = threadIdx.x;
    const int yt = threadIdx.y;

    float v = 0.0f;
#pragma unroll
    for (int s = 0; s < SPLITK/4; ++s)
        v += g_P[(yt*(SPLITK/4) + s)*(B_*NDIM) + b*NDIM + jd];

    __shared__ float red[4][NDIM];
    red[yt][jd] = v;
    __syncthreads();

    if (yt == 0) {
        v = red[0][jd] + red[1][jd] + red[2][jd] + red[3][jd];
        float sq = v*v;
        sq += __shfl_xor_sync(0xffffffffu, sq, 1, 16);
        sq += __shfl_xor_sync(0xffffffffu, sq, 2, 16);
        sq += __shfl_xor_sync(0xffffffffu, sq, 4, 16);
        sq += __shfl_xor_sync(0xffffffffu, sq, 8, 16);   // |s_{b,j}|^2
        float l2  = sqrtf(sq);
        float res = v * (l2 / (1.0f + sq));
        if (use_out) out[b*NDIM + jd] = res;
        else         g_s[b*NDIM + jd] = res;
    }
}

// ---------------------------------------------------------------------------
// G-GEMM: G[ik][jd] = sum_b x[b][ik] * s[b][jd].  M=9216, N=160, K=256.
// grid 144 blocks, 256 threads, KK=16 (16 tiles), register-prefetch dbuf.
__global__ __launch_bounds__(256) void k_ggemm(const float* __restrict__ x) {
    __shared__ float As[2][KK*65];     // [k][m] pad 65
    __shared__ float Ss[2][KK*NDIM];   // [k][n]

    const int tid = threadIdx.x;
    const int tx  = tid & 15;
    const int ty  = tid >> 4;
    const int m0  = blockIdx.x * 64;
    const int lkk = tid >> 6;          // 0..3  (A-load row base)
    const int lmm = tid & 63;          // A-load col

    float acc[4][10];
#pragma unroll
    for (int r = 0; r < 4; ++r)
#pragma unroll
        for (int q = 0; q < 10; ++q) acc[r][q] = 0.0f;

    float ar[4], sr[10];
    {
        const int k0 = 0;
#pragma unroll
        for (int p = 0; p < 4; ++p)
            ar[p] = x[(k0 + lkk + 4*p)*KDIM + m0 + lmm];
#pragma unroll
        for (int p = 0; p < 10; ++p) {
            int idx = tid + 256*p;
            int kk = idx / NDIM, n = idx - kk*NDIM;
            sr[p] = g_s[(k0 + kk)*NDIM + n];
        }
    }

    const int T = B_ / KK;             // 16 tiles
    for (int t = 0; t < T; ++t) {
        const int buf = t & 1;
#pragma unroll
        for (int p = 0; p < 4; ++p)
            As[buf][(lkk + 4*p)*65 + lmm] = ar[p];
#pragma unroll
        for (int p = 0; p < 10; ++p) {
            int idx = tid + 256*p;
            int kk = idx / NDIM, n = idx - kk*NDIM;
            Ss[buf][kk*NDIM + n] = sr[p];
        }
        __syncthreads();

        if (t + 1 < T) {
            const int k0 = (t+1)*KK;
#pragma unroll
            for (int p = 0; p < 4; ++p)
                ar[p] = x[(k0 + lkk + 4*p)*KDIM + m0 + lmm];
#pragma unroll
            for (int p = 0; p < 10; ++p) {
                int idx = tid + 256*p;
                int kk = idx / NDIM, n = idx - kk*NDIM;
                sr[p] = g_s[(k0 + kk)*NDIM + n];
            }
        }

#pragma unroll
        for (int kk = 0; kk < KK; ++kk) {
            float xv[4], sv[10];
#pragma unroll
            for (int r = 0; r < 4; ++r) xv[r] = As[buf][kk*65 + ty*4 + r];
#pragma unroll
            for (int q = 0; q < 10; ++q) sv[q] = Ss[buf][kk*NDIM + tx + 16*q];
#pragma unroll
            for (int r = 0; r < 4; ++r)
#pragma unroll
                for (int q = 0; q < 10; ++q) acc[r][q] += xv[r]*sv[q];
        }
    }

#pragma unroll
    for (int r = 0; r < 4; ++r) {
        int m = m0 + ty*4 + r;
#pragma unroll
        for (int q = 0; q < 10; ++q)
            g_G[m*NDIM + tx + 16*q] = acc[r][q];
    }
}

// ---------------------------------------------------------------------------
// b-update + softmax -> c, then write g_Wc = c * Wt for this i.
// block per i, warp per j (10 warps = 320 threads).
__global__ __launch_bounds__(320) void k_bupdate(const float* __restrict__ W) {
    const int i    = blockIdx.x;
    const int j    = threadIdx.x >> 5;
    const int lane = threadIdx.x & 31;

    const float* Wij = W + ((i*J_ + j)*DOUT)*DIN;    // 128 contiguous floats [d][k]
    float ssum = 0.0f;
#pragma unroll
    for (int t = lane; t < 128; t += 32) {
        int k = t >> 4, d = t & 15;
        ssum += Wij[d*DIN + k] * g_G[(i*DIN + k)*NDIM + j*DOUT + d];
    }
#pragma unroll
    for (int o = 16; o > 0; o >>= 1)
        ssum += __shfl_xor_sync(0xffffffffu, ssum, o);

    __shared__ float dj[J_];
    __shared__ float cs[J_];
    if (lane == 0) dj[j] = ssum;
    __syncthreads();

    if (threadIdx.x == 0) {
        float bb[J_];
        float mx = -1e30f;
#pragma unroll
        for (int jj = 0; jj < J_; ++jj) {
            bb[jj] = g_b[i*J_ + jj] + dj[jj];
            g_b[i*J_ + jj] = bb[jj];
            mx = fmaxf(mx, bb[jj]);
        }
        float sum = 0.0f;
#pragma unroll
        for (int jj = 0; jj < J_; ++jj) { bb[jj] = expf(bb[jj] - mx); sum += bb[jj]; }
        float inv = 1.0f / sum;
#pragma unroll
        for (int jj = 0; jj < J_; ++jj) cs[jj] = bb[jj] * inv;
    }
    __syncthreads();

    // write coupling-scaled weights for next S-GEMM: 8 rows x 160 cols
    const int base = (i*DIN)*NDIM;
#pragma unroll
    for (int t = threadIdx.x; t < DIN*NDIM; t += 320) {
        int col = t % NDIM;
        g_Wc[base + t] = g_Wt[base + t] * cs[col >> 4];
    }
}

// ---------------------------------------------------------------------------
extern "C" void kernel_launch(void* const* d_in, const int* in_sizes, int n_in,
                              void* d_out, int out_size) {
    const float* x = (const float*)d_in[0];   // [256, 1152, 8]
    const float* W = (const float*)d_in[1];   // [1152, 10, 16, 8]
    float* out = (float*)d_out;               // [256, 10, 16]

    k_wtinit<<<(KDIM*NDIM + 255)/256, 256>>>(W);

    for (int iter = 0; iter < 3; ++iter) {
        k_sgemm<<<dim3(4, SPLITK), 256>>>(x);
        k_redsquash<<<B_, dim3(NDIM, 4)>>>(out, iter == 2 ? 1 : 0);
        if (iter < 2) {
            k_ggemm<<<KDIM/64, 256>>>(x);
            k_bupdate<<<I_, 320>>>(W);
        }
    }
}